// round 8
// baseline (speedup 1.0000x reference)
#include <cuda_runtime.h>
#include <cuda_fp16.h>
#include <math.h>
#include <stdint.h>

// Problem constants
#define Bq    8
#define Tt    512
#define BT    4096      // B*T
#define Dd    1024
#define Hh    16
#define KVHh  4
#define HDd   64
#define Ll    4
#define Vv    32000
#define FFd   4096
#define QKVD  1536      // H*HD + 2*KVH*HD

typedef __half f16;

// ---------------------------------------------------------------------------
// Scratch (static device globals; no allocations allowed)
// ---------------------------------------------------------------------------
__device__ float g_x[BT * Dd];        // residual stream (fp32)
__device__ float g_qkv[BT * QKVD];    // qkv projection (rope in place, fp32)

__device__ f16 g_h[BT * Dd];          // layernorm output (fp16)
__device__ f16 g_y[BT * Dd];          // attention output (fp16)
__device__ f16 g_mlp[BT * FFd];       // gelu(fc) output (fp16)

// Transposed + split weights ([N][K] layout, fp16 hi/lo)
__device__ f16 g_wqkv_hi[Ll * QKVD * Dd];
__device__ f16 g_wqkv_lo[Ll * QKVD * Dd];
__device__ f16 g_wap_hi [Ll * Dd * Dd];
__device__ f16 g_wap_lo [Ll * Dd * Dd];
__device__ f16 g_wfc_hi [Ll * FFd * Dd];
__device__ f16 g_wfc_lo [Ll * FFd * Dd];
__device__ f16 g_wmp_hi [Ll * Dd * FFd];
__device__ f16 g_wmp_lo [Ll * Dd * FFd];
__device__ f16 g_wlm_hi [Vv * Dd];
__device__ f16 g_wlm_lo [Vv * Dd];

// ---------------------------------------------------------------------------
// Weight transpose + split:  W[K][N] fp32  ->  out[N][K] fp16 hi/lo
// ---------------------------------------------------------------------------
__global__ void wconv_kernel(const float* __restrict__ W,
                             f16* __restrict__ oh, f16* __restrict__ ol,
                             int K, int N) {
    __shared__ float tile[32][33];
    int z = blockIdx.z;
    const float* Wz = W + (size_t)z * K * N;
    size_t ob = (size_t)z * K * N;
    int kb = blockIdx.y * 32, nb = blockIdx.x * 32;
    int tx = threadIdx.x, ty = threadIdx.y;
#pragma unroll
    for (int i = 0; i < 4; i++)
        tile[ty + 8 * i][tx] = Wz[(size_t)(kb + ty + 8 * i) * N + nb + tx];
    __syncthreads();
#pragma unroll
    for (int i = 0; i < 4; i++) {
        float v = tile[tx][ty + 8 * i];
        f16 h = __float2half_rn(v);
        f16 l = __float2half_rn(v - __half2float(h));
        size_t o = ob + (size_t)(nb + ty + 8 * i) * K + kb + tx;
        oh[o] = h; ol[o] = l;
    }
}

// ---------------------------------------------------------------------------
// Embedding gather
// ---------------------------------------------------------------------------
__global__ void embed_kernel(const int* __restrict__ ids,
                             const float* __restrict__ wte,
                             float* __restrict__ x) {
    int row = blockIdx.x;
    int tok = ids[row];
    const float4* src = (const float4*)(wte + (size_t)tok * Dd);
    float4* dst = (float4*)(x + (size_t)row * Dd);
    for (int i = threadIdx.x; i < Dd / 4; i += blockDim.x) dst[i] = src[i];
}

// ---------------------------------------------------------------------------
// LayerNorm -> fp16
// ---------------------------------------------------------------------------
__global__ void ln_kernel(const float* __restrict__ x,
                          const float* __restrict__ gamma,
                          const float* __restrict__ beta,
                          f16* __restrict__ oh) {
    int row = blockIdx.x;
    const float* xr = x + (size_t)row * Dd;
    int t = threadIdx.x;
    float v[4];
    float s = 0.f, sq = 0.f;
#pragma unroll
    for (int i = 0; i < 4; i++) {
        float val = xr[t + i * 256];
        v[i] = val; s += val; sq += val * val;
    }
#pragma unroll
    for (int o = 16; o > 0; o >>= 1) {
        s  += __shfl_xor_sync(0xFFFFFFFFu, s, o);
        sq += __shfl_xor_sync(0xFFFFFFFFu, sq, o);
    }
    __shared__ float ss[8], sqq[8];
    int wid = t >> 5, lane = t & 31;
    if (lane == 0) { ss[wid] = s; sqq[wid] = sq; }
    __syncthreads();
    if (t == 0) {
        float a = 0.f, b = 0.f;
#pragma unroll
        for (int i = 0; i < 8; i++) { a += ss[i]; b += sqq[i]; }
        ss[0] = a; sqq[0] = b;
    }
    __syncthreads();
    float mean = ss[0] * (1.0f / Dd);
    float var  = sqq[0] * (1.0f / Dd) - mean * mean;
    float inv  = rsqrtf(var + 1e-5f);
#pragma unroll
    for (int i = 0; i < 4; i++) {
        int c = t + i * 256;
        float o = (v[i] - mean) * inv * gamma[c] + beta[c];
        oh[(size_t)row * Dd + c] = __float2half_rn(o);
    }
}

// ---------------------------------------------------------------------------
// RoPE in place on qkv (fp32)
// ---------------------------------------------------------------------------
__global__ void rope_kernel(float* __restrict__ qkv) {
    int row = blockIdx.x;
    int t = row % Tt;
    float* qr = qkv + (size_t)row * QKVD;
    const float ft = (float)t;
    for (int idx = threadIdx.x; idx < (Hh + KVHh) * (HDd / 2); idx += blockDim.x) {
        int head = idx >> 5;
        int i    = idx & 31;
        int base = (head < Hh) ? head * HDd : Dd + (head - Hh) * HDd;
        float inv = expf(-((2.0f * i) / (float)HDd) * 9.210340371976184f);
        float ang = ft * inv;
        float c, s;
        sincosf(ang, &s, &c);
        float u0 = qr[base + 2 * i];
        float u1 = qr[base + 2 * i + 1];
        qr[base + 2 * i]     = u0 * c - u1 * s;
        qr[base + 2 * i + 1] = u0 * s + u1 * c;
    }
}

// ---------------------------------------------------------------------------
// Causal flash attention: 256 threads = 64 q-rows x 4 GQA heads sharing one
// KV head's tiles. Tile-max softmax (one rescale per 64-key tile).
// grid: (T/64, KVH, B).
// ---------------------------------------------------------------------------
#define ATTN_SMEM ((4096 + 4096 + 4 * 64 * 65) * 4)

__global__ void __launch_bounds__(256) attn_kernel(const float* __restrict__ qkv,
                                                   f16* __restrict__ y) {
    extern __shared__ float asm_[];
    float* Ks = asm_;                 // [64][64]
    float* Vs = asm_ + 4096;          // [64][64]
    float* S  = asm_ + 8192;          // [4][64][65]

    int qt = blockIdx.x, kvh = blockIdx.y, b = blockIdx.z;
    int tid = threadIdx.x;
    int qr = tid & 63;                // query row within tile
    int hsub = tid >> 6;              // 0..3
    int h = kvh * 4 + hsub;           // q head (h/4 == kvh)
    int qglob = qt * 64 + qr;
    int qrow = b * Tt + qglob;
    const float* qp = qkv + (size_t)qrow * QKVD + h * HDd;

    float q[HDd];
#pragma unroll
    for (int d = 0; d < HDd; d++) q[d] = qp[d];
    float acc[HDd];
#pragma unroll
    for (int d = 0; d < HDd; d++) acc[d] = 0.f;
    float m = -1e30f, l = 0.f;

    float* Srow = S + (hsub * 64 + qr) * 65;

    const float* Kbase = qkv + (size_t)(b * Tt) * QKVD + Dd + kvh * HDd;
    const float* Vbase = Kbase + KVHh * HDd;
    const float scale = 0.125f;

    for (int kt = 0; kt <= qt; kt++) {
        const float* Kb = Kbase + (size_t)kt * 64 * QKVD;
        const float* Vb = Vbase + (size_t)kt * 64 * QKVD;
        __syncthreads();
        for (int id = tid; id < 2048; id += 256) {
            int r = (id & 1023) >> 4, dg = id & 15;
            float* dst = (id < 1024) ? Ks : Vs;
            const float* src = (id < 1024) ? Kb : Vb;
            ((float4*)(dst + r * 64))[dg] = *(const float4*)(src + (size_t)r * QKVD + dg * 4);
        }
        __syncthreads();
        int jmax = (kt == qt) ? (qr + 1) : 64;
        float tmax = -1e30f;
        for (int j = 0; j < jmax; j++) {
            float s = 0.f;
            const float* kr = Ks + j * 64;
#pragma unroll
            for (int d = 0; d < HDd; d++) s += q[d] * kr[d];
            s *= scale;
            Srow[j] = s;
            tmax = fmaxf(tmax, s);
        }
        if (tmax > m) {
            float corr = __expf(m - tmax);
            l *= corr;
#pragma unroll
            for (int d = 0; d < HDd; d++) acc[d] *= corr;
            m = tmax;
        }
        for (int j = 0; j < jmax; j++) {
            float p = __expf(Srow[j] - m);
            l += p;
            const float* vr = Vs + j * 64;
#pragma unroll
            for (int d = 0; d < HDd; d++) acc[d] += p * vr[d];
        }
    }
    float invl = 1.f / l;
    size_t yo = (size_t)qrow * Dd + h * HDd;
#pragma unroll
    for (int d = 0; d < HDd; d++)
        y[yo + d] = __float2half_rn(acc[d] * invl);
}

// ---------------------------------------------------------------------------
// GEMM (2-pass fp16 compensated): C[M,N] = A[M,K] @ W[N,K]^T (+bias, epilogue)
//   A fp16 single;  W split hi+lo.  C = A*Wh + A*Wl  (fp32 accumulate)
// Grid: (BT/128, N/256), 256 threads.
//   - tcgen05 path (feature arch): tile 128x256, BK=64, TMEM accum
//   - mma.sync fallback: two 128-col halves, BK=32, 2-stage, warp tile 64x32,
//     ldmatrix fragment loads (conflict-free with LDA=40)
// EPI 0: bias + fp32 out.  EPI 1: bias + GELU + fp16 out.  EPI 2: bias+res+fp32.
// ---------------------------------------------------------------------------
#if defined(__CUDA_ARCH_FEAT_SM103_ALL) || defined(__CUDA_ARCH_FEAT_SM100_ALL) || defined(__CUDA_ARCH_FEAT_SM101_ALL)
#define HAS_TCGEN05 1
#else
#define HAS_TCGEN05 0
#endif

#define TM 128
#define TN 256
// tcgen05 path smem: A 16KB + Wh 32KB + Wl 32KB per stage, 2 stages, +1KB ctrl
#define TC_STG   81920u
#define TC_OFF_A 0u
#define TC_OFF_BH 16384u
#define TC_OFF_BL 49152u
#define TILE_OFF 1024u
#define GEMM_SMEM_TOTAL (1024 + 2 * 81920)

// idesc kind::f16 (fp16 in, fp32 accum): dtype=F32(1<<4), atype=btype=F16(0)
#define GEMM_IDESC ((1u << 4) | ((TN / 8u) << 17) | ((TM / 16u) << 24))

// SW128 descriptor: layout=2, version=1, SBO=64, LBO=1
#define DESC_BASE ((2ull << 61) | (1ull << 46) | (64ull << 32) | (1ull << 16))
#define MAKE_DESC(addr) (DESC_BASE | (((uint64_t)((addr) >> 4)) & 0x3FFF))

__device__ __forceinline__ void cpasync16(uint32_t d, const void* src) {
    asm volatile("cp.async.cg.shared.global [%0], [%1], 16;\n" :: "r"(d), "l"(src));
}
__device__ __forceinline__ void cpasync16p(void* dst, const void* src) {
    uint32_t d = (uint32_t)__cvta_generic_to_shared(dst);
    asm volatile("cp.async.cg.shared.global [%0], [%1], 16;\n" :: "r"(d), "l"(src));
}

#define MMAF16(d, a, b)                                                       \
    asm volatile(                                                             \
        "mma.sync.aligned.m16n8k16.row.col.f32.f16.f16.f32 "                  \
        "{%0,%1,%2,%3}, {%4,%5,%6,%7}, {%8,%9}, {%0,%1,%2,%3};"               \
        : "+f"((d)[0]), "+f"((d)[1]), "+f"((d)[2]), "+f"((d)[3])              \
        : "r"((a)[0]), "r"((a)[1]), "r"((a)[2]), "r"((a)[3]),                 \
          "r"((b)[0]), "r"((b)[1]))

__device__ __forceinline__ void ldsm_x4(uint32_t& r0, uint32_t& r1,
                                        uint32_t& r2, uint32_t& r3, uint32_t a) {
    asm volatile("ldmatrix.sync.aligned.m8n8.x4.shared.b16 {%0,%1,%2,%3}, [%4];"
                 : "=r"(r0), "=r"(r1), "=r"(r2), "=r"(r3) : "r"(a));
}

#if HAS_TCGEN05
__device__ __forceinline__ void tc_mma(uint32_t d, uint64_t a, uint64_t b, uint32_t en) {
    asm volatile(
        "{\n\t.reg .pred p;\n\tsetp.ne.u32 p, %4, 0;\n\t"
        "tcgen05.mma.cta_group::1.kind::f16 [%0], %1, %2, %3, {%5,%5,%5,%5}, p;\n\t}"
        :: "r"(d), "l"(a), "l"(b), "r"(GEMM_IDESC), "r"(en), "r"(0u) : "memory");
}
__device__ __forceinline__ void mbar_wait(uint32_t mbar, uint32_t parity) {
    uint32_t done;
    asm volatile(
        "{\n\t.reg .pred p;\n\t"
        "mbarrier.try_wait.parity.acquire.cta.shared::cta.b64 p, [%1], %2;\n\t"
        "selp.b32 %0, 1, 0, p;\n\t}"
        : "=r"(done) : "r"(mbar), "r"(parity) : "memory");
    if (!done) {
        asm volatile(
            "{\n\t.reg .pred P1;\n\t"
            "WL_%=:\n\t"
            "mbarrier.try_wait.parity.acquire.cta.shared::cta.b64 P1, [%0], %1, 0x989680;\n\t"
            "@P1 bra.uni WD_%=;\n\t"
            "bra.uni WL_%=;\n\t"
            "WD_%=:\n\t}"
            :: "r"(mbar), "r"(parity) : "memory");
    }
}
__device__ __forceinline__ void tc_load_stage(
    uint32_t stg, const f16* A, const f16* Wh, const f16* Wl,
    int rowBase, int colBase, int K, int kt, int tid) {
    for (int id = tid; id < 5120; id += 256) {
        const f16* src; uint32_t off; int r, c, rg;
        if (id < 1024) {
            r = id >> 3; c = id & 7;
            src = A; off = TC_OFF_A; rg = rowBase + r;
        } else {
            int t2 = id - 1024;
            int q = t2 & 2047; r = q >> 3; c = q & 7;
            bool hi = t2 < 2048;
            src = hi ? Wh : Wl; off = hi ? TC_OFF_BH : TC_OFF_BL;
            rg = colBase + r;
        }
        int bo = r * 128 + c * 16;
        uint32_t sw = (uint32_t)(bo ^ ((bo >> 3) & 0x70));
        cpasync16(stg + off + sw, src + (size_t)rg * K + kt + c * 8);
    }
}
#endif

template <int EPI>
__global__ void __launch_bounds__(256) gemm_any(
    const f16* __restrict__ A, const f16* __restrict__ Wh, const f16* __restrict__ Wl,
    const float* __restrict__ bias, const float* __restrict__ res,
    float* __restrict__ C, f16* __restrict__ Cout, int N, int K) {
    extern __shared__ __align__(1024) char sm[];
    const int tid = threadIdx.x;
    const int wid = tid >> 5, lane = tid & 31;
    const int rowBase = blockIdx.x * TM;
    const int colBase = blockIdx.y * TN;

#if HAS_TCGEN05
    // ---------------- tcgen05 path ----------------
    uint32_t smb;
    asm("{ .reg .u64 t; cvta.to.shared.u64 t, %1; cvt.u32.u64 %0, t; }"
        : "=r"(smb) : "l"(sm));
    if (wid == 0)
        asm volatile("tcgen05.alloc.cta_group::1.sync.aligned.shared::cta.b32 [%0], %1;"
                     :: "r"(smb), "r"(256) : "memory");
    if (tid == 0) {
        asm volatile("mbarrier.init.shared.b64 [%0], 1;" :: "r"(smb + 8)  : "memory");
        asm volatile("mbarrier.init.shared.b64 [%0], 1;" :: "r"(smb + 16) : "memory");
    }
    __syncthreads();
    uint32_t tmem;
    asm volatile("ld.shared.b32 %0, [%1];" : "=r"(tmem) : "r"(smb));

    const int niter = K >> 6;
    tc_load_stage(smb + TILE_OFF, A, Wh, Wl, rowBase, colBase, K, 0, tid);
    asm volatile("cp.async.commit_group;");
    tc_load_stage(smb + TILE_OFF + TC_STG, A, Wh, Wl, rowBase, colBase, K, 64, tid);
    asm volatile("cp.async.commit_group;");

    for (int it = 0; it < niter; ++it) {
        const int s = it & 1;
        const uint32_t stg = smb + TILE_OFF + s * TC_STG;
        asm volatile("cp.async.wait_group 1;");
        __syncthreads();
        if (tid == 0) {
            asm volatile("fence.proxy.async.shared::cta;" ::: "memory");
            uint64_t ad = MAKE_DESC(stg + TC_OFF_A);
            uint64_t bh = MAKE_DESC(stg + TC_OFF_BH);
            uint64_t bl = MAKE_DESC(stg + TC_OFF_BL);
#pragma unroll
            for (int k = 0; k < 4; ++k) {
                tc_mma(tmem, ad + k * 2, bh + k * 2, (it | k) ? 1u : 0u);
                tc_mma(tmem, ad + k * 2, bl + k * 2, 1u);
            }
            asm volatile(
                "tcgen05.commit.cta_group::1.mbarrier::arrive::one.shared::cluster.b64 [%0];"
                :: "r"(smb + 8 + s * 8) : "memory");
        }
        mbar_wait(smb + 8 + s * 8, (uint32_t)((it >> 1) & 1));
        if (it + 2 < niter)
            tc_load_stage(stg, A, Wh, Wl, rowBase, colBase, K, (it + 2) * 64, tid);
        asm volatile("cp.async.commit_group;");
    }
    __syncthreads();
    asm volatile("tcgen05.fence::after_thread_sync;" ::: "memory");

    float* tsm = (float*)(sm + TILE_OFF) + wid * (32 * 33);
    const int sub = wid & 3;
    const int cwbase = (wid >= 4) ? 128 : 0;
#pragma unroll 1
    for (int ch = 0; ch < 4; ++ch) {
        int c0 = cwbase + ch * 32;
        uint32_t d[32];
        asm volatile(
            "tcgen05.ld.sync.aligned.32x32b.x32.b32 "
            "{%0,%1,%2,%3,%4,%5,%6,%7,%8,%9,%10,%11,%12,%13,%14,%15,"
            "%16,%17,%18,%19,%20,%21,%22,%23,%24,%25,%26,%27,%28,%29,%30,%31}, [%32];"
            : "=r"(d[0]), "=r"(d[1]), "=r"(d[2]), "=r"(d[3]), "=r"(d[4]), "=r"(d[5]),
              "=r"(d[6]), "=r"(d[7]), "=r"(d[8]), "=r"(d[9]), "=r"(d[10]), "=r"(d[11]),
              "=r"(d[12]), "=r"(d[13]), "=r"(d[14]), "=r"(d[15]), "=r"(d[16]), "=r"(d[17]),
              "=r"(d[18]), "=r"(d[19]), "=r"(d[20]), "=r"(d[21]), "=r"(d[22]), "=r"(d[23]),
              "=r"(d[24]), "=r"(d[25]), "=r"(d[26]), "=r"(d[27]), "=r"(d[28]), "=r"(d[29]),
              "=r"(d[30]), "=r"(d[31])
            : "r"(tmem + c0));
        asm volatile("tcgen05.wait::ld.sync.aligned;" ::: "memory");
#pragma unroll
        for (int j = 0; j < 32; ++j) {
            float x = __uint_as_float(d[j]);
            if (bias) x += bias[colBase + c0 + j];
            if (EPI == 1) x = 0.5f * x * (1.f + erff(x * 0.70710678118654752f));
            tsm[lane * 33 + j] = x;
        }
        __syncwarp();
#pragma unroll
        for (int jj = 0; jj < 32; ++jj) {
            int r = rowBase + sub * 32 + jj;
            int c = colBase + c0 + lane;
            float val = tsm[jj * 33 + lane];
            if (EPI == 1) {
                Cout[(size_t)r * N + c] = __float2half_rn(val);
            } else {
                if (EPI == 2) val += res[(size_t)r * N + c];
                C[(size_t)r * N + c] = val;
            }
        }
        __syncwarp();
    }
    __syncthreads();
    if (wid == 0)
        asm volatile("tcgen05.dealloc.cta_group::1.sync.aligned.b32 %0, %1;"
                     :: "r"(tmem), "r"(256));

#else
    // -------- mma.sync fallback: two 128-col halves, BK=32, ldmatrix --------
    const int warpM = wid >> 2, warpN = wid & 3;   // 2 x 4 warps, tile 64x32
    f16* smh = (f16*)sm;
    const uint32_t smbase = (uint32_t)__cvta_generic_to_shared(smh);
    const int LDA = 40;           // 32 + 8 pad (halves)
    const int SCH = 128 * 40;     // halves per array (5120)
    const int SST = 3 * SCH;      // halves per stage (15360)
    const int niter = K >> 5;

    for (int hf = 0; hf < 2; ++hf) {
        const int cb = colBase + hf * 128;
        float acc[4][4][4];
#pragma unroll
        for (int a = 0; a < 4; a++)
#pragma unroll
            for (int b = 0; b < 4; b++)
#pragma unroll
                for (int c = 0; c < 4; c++) acc[a][b][c] = 0.f;

#define FB_PREFETCH(stage, kt)                                                \
        {                                                                     \
            f16* sb = smh + (stage) * SST;                                    \
            _Pragma("unroll")                                                 \
            for (int u = 0; u < 6; ++u) {                                     \
                int id = tid + u * 256;                                       \
                int arr = id >> 9;                                            \
                int q = id & 511;                                             \
                int r = q >> 2, seg = q & 3;                                  \
                const f16* src = (arr == 0) ? A : ((arr == 1) ? Wh : Wl);     \
                int rg = ((arr == 0) ? rowBase : cb) + r;                     \
                cpasync16p(sb + arr * SCH + r * LDA + seg * 8,                \
                           src + (size_t)rg * K + (kt) + seg * 8);            \
            }                                                                 \
            asm volatile("cp.async.commit_group;");                           \
        }

        FB_PREFETCH(0, 0);

        for (int it = 0; it < niter; ++it) {
            if (it + 1 < niter) {
                FB_PREFETCH((it + 1) & 1, (it + 1) << 5);
                asm volatile("cp.async.wait_group 1;");
            } else {
                asm volatile("cp.async.wait_group 0;");
            }
            __syncthreads();

            const uint32_t base = smbase + (uint32_t)((it & 1) * SST) * 2;
            const uint32_t baseA  = base;
            const uint32_t baseBh = base + (uint32_t)SCH * 2;
            const uint32_t baseBl = base + (uint32_t)(2 * SCH) * 2;

#pragma unroll
            for (int k0 = 0; k0 < 32; k0 += 16) {
                uint32_t ah[4][4], bh[4][2], bl[4][2];
                // A frags: ldmatrix.x4, rows warpM*64+mt*16+(lane&15), chunk lane>>4
                {
                    int arow = warpM * 64 + (lane & 15);
                    int acol = k0 + (lane >> 4) * 8;
#pragma unroll
                    for (int mt = 0; mt < 4; ++mt) {
                        uint32_t addr = baseA + (uint32_t)(((arow + mt * 16) * LDA + acol) * 2);
                        ldsm_x4(ah[mt][0], ah[mt][1], ah[mt][2], ah[mt][3], addr);
                    }
                }
                // B frags: ldmatrix.x4 covering nt pairs (2 tiles x 2 chunks)
                {
                    int brow = (lane & 7) + ((lane >> 4) << 3);   // 0..15
                    int bcol = k0 + (((lane >> 3) & 1) << 3);
#pragma unroll
                    for (int p = 0; p < 2; ++p) {
                        int n0 = warpN * 32 + p * 16;
                        uint32_t ah_ = baseBh + (uint32_t)(((n0 + brow) * LDA + bcol) * 2);
                        ldsm_x4(bh[2 * p][0], bh[2 * p][1], bh[2 * p + 1][0], bh[2 * p + 1][1], ah_);
                        uint32_t al_ = baseBl + (uint32_t)(((n0 + brow) * LDA + bcol) * 2);
                        ldsm_x4(bl[2 * p][0], bl[2 * p][1], bl[2 * p + 1][0], bl[2 * p + 1][1], al_);
                    }
                }
                // hi pass then lo pass
#pragma unroll
                for (int mt = 0; mt < 4; ++mt)
#pragma unroll
                    for (int nt = 0; nt < 4; ++nt)
                        MMAF16(acc[mt][nt], ah[mt], bh[nt]);
#pragma unroll
                for (int mt = 0; mt < 4; ++mt)
#pragma unroll
                    for (int nt = 0; nt < 4; ++nt)
                        MMAF16(acc[mt][nt], ah[mt], bl[nt]);
            }
            __syncthreads();
        }
#undef FB_PREFETCH

        // Epilogue for this half
#pragma unroll
        for (int mt = 0; mt < 4; ++mt) {
#pragma unroll
            for (int nt = 0; nt < 4; ++nt) {
                int r0 = rowBase + warpM * 64 + mt * 16 + (lane >> 2);
                int c0 = cb + warpN * 32 + nt * 8 + (lane & 3) * 2;
                float v0 = acc[mt][nt][0], v1 = acc[mt][nt][1];
                float v2 = acc[mt][nt][2], v3 = acc[mt][nt][3];
                if (bias) {
                    float b0 = bias[c0], b1 = bias[c0 + 1];
                    v0 += b0; v1 += b1; v2 += b0; v3 += b1;
                }
                if (EPI == 1) {
                    v0 = 0.5f * v0 * (1.f + erff(v0 * 0.70710678118654752f));
                    v1 = 0.5f * v1 * (1.f + erff(v1 * 0.70710678118654752f));
                    v2 = 0.5f * v2 * (1.f + erff(v2 * 0.70710678118654752f));
                    v3 = 0.5f * v3 * (1.f + erff(v3 * 0.70710678118654752f));
                    __half2 p0, p1;
                    p0.x = __float2half_rn(v0); p0.y = __float2half_rn(v1);
                    p1.x = __float2half_rn(v2); p1.y = __float2half_rn(v3);
                    *(__half2*)(Cout + (size_t)r0 * N + c0) = p0;
                    *(__half2*)(Cout + (size_t)(r0 + 8) * N + c0) = p1;
                } else {
                    if (EPI == 2) {
                        float2 ra = *(const float2*)(res + (size_t)r0 * N + c0);
                        float2 rb = *(const float2*)(res + (size_t)(r0 + 8) * N + c0);
                        v0 += ra.x; v1 += ra.y; v2 += rb.x; v3 += rb.y;
                    }
                    float2 o0; o0.x = v0; o0.y = v1;
                    float2 o1; o1.x = v2; o1.y = v3;
                    *(float2*)(C + (size_t)r0 * N + c0) = o0;
                    *(float2*)(C + (size_t)(r0 + 8) * N + c0) = o1;
                }
            }
        }
        __syncthreads();
    }
#endif
}

// ---------------------------------------------------------------------------
// Launch
// ---------------------------------------------------------------------------
extern "C" void kernel_launch(void* const* d_in, const int* in_sizes, int n_in,
                              void* d_out, int out_size) {
    const int*   ids      = (const int*)d_in[0];
    const float* wte      = (const float*)d_in[1];
    const float* ln1_g    = (const float*)d_in[2];
    const float* ln1_b    = (const float*)d_in[3];
    const float* c_attn_w = (const float*)d_in[4];
    const float* c_attn_b = (const float*)d_in[5];
    const float* c_proj_w = (const float*)d_in[6];
    const float* c_proj_b = (const float*)d_in[7];
    const float* ln2_g    = (const float*)d_in[8];
    const float* ln2_b    = (const float*)d_in[9];
    const float* fc_w     = (const float*)d_in[10];
    const float* fc_b     = (const float*)d_in[11];
    const float* proj_w   = (const float*)d_in[12];
    const float* proj_b   = (const float*)d_in[13];
    const float* lnf_g    = (const float*)d_in[14];
    const float* lnf_b    = (const float*)d_in[15];
    const float* lm_w     = (const float*)d_in[16];
    float* out = (float*)d_out;

    float *x, *qkv;
    f16 *h, *y, *mlp;
    f16 *wqkv_hi, *wqkv_lo, *wap_hi, *wap_lo, *wfc_hi, *wfc_lo;
    f16 *wmp_hi, *wmp_lo, *wlm_hi, *wlm_lo;
    cudaGetSymbolAddress((void**)&x,    g_x);
    cudaGetSymbolAddress((void**)&qkv,  g_qkv);
    cudaGetSymbolAddress((void**)&h,    g_h);
    cudaGetSymbolAddress((void**)&y,    g_y);
    cudaGetSymbolAddress((void**)&mlp,  g_mlp);
    cudaGetSymbolAddress((void**)&wqkv_hi, g_wqkv_hi);
    cudaGetSymbolAddress((void**)&wqkv_lo, g_wqkv_lo);
    cudaGetSymbolAddress((void**)&wap_hi,  g_wap_hi);
    cudaGetSymbolAddress((void**)&wap_lo,  g_wap_lo);
    cudaGetSymbolAddress((void**)&wfc_hi,  g_wfc_hi);
    cudaGetSymbolAddress((void**)&wfc_lo,  g_wfc_lo);
    cudaGetSymbolAddress((void**)&wmp_hi,  g_wmp_hi);
    cudaGetSymbolAddress((void**)&wmp_lo,  g_wmp_lo);
    cudaGetSymbolAddress((void**)&wlm_hi,  g_wlm_hi);
    cudaGetSymbolAddress((void**)&wlm_lo,  g_wlm_lo);

    cudaFuncSetAttribute(gemm_any<0>, cudaFuncAttributeMaxDynamicSharedMemorySize, GEMM_SMEM_TOTAL);
    cudaFuncSetAttribute(gemm_any<1>, cudaFuncAttributeMaxDynamicSharedMemorySize, GEMM_SMEM_TOTAL);
    cudaFuncSetAttribute(gemm_any<2>, cudaFuncAttributeMaxDynamicSharedMemorySize, GEMM_SMEM_TOTAL);
    cudaFuncSetAttribute(attn_kernel, cudaFuncAttributeMaxDynamicSharedMemorySize, ATTN_SMEM);

    dim3 t32x8(32, 8);

    // Weight conversion (transpose + split)
    wconv_kernel<<<dim3(QKVD / 32, Dd / 32, Ll), t32x8>>>(c_attn_w, wqkv_hi, wqkv_lo, Dd, QKVD);
    wconv_kernel<<<dim3(Dd / 32, Dd / 32, Ll),   t32x8>>>(c_proj_w, wap_hi,  wap_lo,  Dd, Dd);
    wconv_kernel<<<dim3(FFd / 32, Dd / 32, Ll),  t32x8>>>(fc_w,     wfc_hi,  wfc_lo,  Dd, FFd);
    wconv_kernel<<<dim3(Dd / 32, FFd / 32, Ll),  t32x8>>>(proj_w,   wmp_hi,  wmp_lo,  FFd, Dd);
    wconv_kernel<<<dim3(Vv / 32, Dd / 32, 1),    t32x8>>>(lm_w,     wlm_hi,  wlm_lo,  Dd, Vv);

    embed_kernel<<<BT, 256>>>(ids, wte, x);

    for (int l = 0; l < Ll; l++) {
        // LN1 -> h (fp16)
        ln_kernel<<<BT, 256>>>(x, ln1_g + (size_t)l * Dd, ln1_b + (size_t)l * Dd, h);
        // QKV projection (fp32 out)
        gemm_any<0><<<dim3(BT / TM, QKVD / TN), 256, GEMM_SMEM_TOTAL>>>(
            h, wqkv_hi + (size_t)l * QKVD * Dd, wqkv_lo + (size_t)l * QKVD * Dd,
            c_attn_b + (size_t)l * QKVD, nullptr, qkv, nullptr, QKVD, Dd);
        // RoPE
        rope_kernel<<<BT, 256>>>(qkv);
        // Attention -> y (fp16)
        attn_kernel<<<dim3(Tt / 64, KVHh, Bq), 256, ATTN_SMEM>>>(qkv, y);
        // Attn out projection + residual (fp32 into x)
        gemm_any<2><<<dim3(BT / TM, Dd / TN), 256, GEMM_SMEM_TOTAL>>>(
            y, wap_hi + (size_t)l * Dd * Dd, wap_lo + (size_t)l * Dd * Dd,
            c_proj_b + (size_t)l * Dd, x, x, nullptr, Dd, Dd);
        // LN2 -> h (fp16)
        ln_kernel<<<BT, 256>>>(x, ln2_g + (size_t)l * Dd, ln2_b + (size_t)l * Dd, h);
        // FC + GELU -> mlp (fp16)
        gemm_any<1><<<dim3(BT / TM, FFd / TN), 256, GEMM_SMEM_TOTAL>>>(
            h, wfc_hi + (size_t)l * FFd * Dd, wfc_lo + (size_t)l * FFd * Dd,
            fc_b + (size_t)l * FFd, nullptr, nullptr, mlp, FFd, Dd);
        // MLP projection + residual (fp32 into x)
        gemm_any<2><<<dim3(BT / TM, Dd / TN), 256, GEMM_SMEM_TOTAL>>>(
            mlp, wmp_hi + (size_t)l * Dd * FFd, wmp_lo + (size_t)l * Dd * FFd,
            proj_b + (size_t)l * Dd, x, x, nullptr, Dd, FFd);
    }

    // Final LN + LM head
    ln_kernel<<<BT, 256>>>(x, lnf_g, lnf_b, h);
    gemm_any<0><<<dim3(BT / TM, Vv / TN), 256, GEMM_SMEM_TOTAL>>>(
        h, wlm_hi, wlm_lo, nullptr, nullptr, out, nullptr, Vv, Dd);
}

// round 9
// speedup vs baseline: 1.6977x; 1.6977x over previous
#include <cuda_runtime.h>
#include <cuda_fp16.h>
#include <math.h>
#include <stdint.h>

// Problem constants
#define Bq    8
#define Tt    512
#define BT    4096      // B*T
#define Dd    1024
#define Hh    16
#define KVHh  4
#define HDd   64
#define Ll    4
#define Vv    32000
#define FFd   4096
#define QKVD  1536      // H*HD + 2*KVH*HD

typedef __half f16;

// ---------------------------------------------------------------------------
// Scratch (static device globals; no allocations allowed)
// ---------------------------------------------------------------------------
__device__ float g_x[BT * Dd];        // residual stream (fp32)
__device__ float g_qkv[BT * QKVD];    // qkv projection (rope in place, fp32)

__device__ f16 g_h[BT * Dd];          // layernorm output (fp16)
__device__ f16 g_y[BT * Dd];          // attention output (fp16)
__device__ f16 g_mlp[BT * FFd];       // gelu(fc) output (fp16)

// Transposed + split weights ([N][K] layout, fp16 hi/lo)
__device__ f16 g_wqkv_hi[Ll * QKVD * Dd];
__device__ f16 g_wqkv_lo[Ll * QKVD * Dd];
__device__ f16 g_wap_hi [Ll * Dd * Dd];
__device__ f16 g_wap_lo [Ll * Dd * Dd];
__device__ f16 g_wfc_hi [Ll * FFd * Dd];
__device__ f16 g_wfc_lo [Ll * FFd * Dd];
__device__ f16 g_wmp_hi [Ll * Dd * FFd];
__device__ f16 g_wmp_lo [Ll * Dd * FFd];
__device__ f16 g_wlm_hi [Vv * Dd];
__device__ f16 g_wlm_lo [Vv * Dd];   // unused (LM head single-pass), kept for layout

// ---------------------------------------------------------------------------
// Weight transpose + split:  W[K][N] fp32  ->  out[N][K] fp16 hi/lo
// ---------------------------------------------------------------------------
__global__ void wconv_kernel(const float* __restrict__ W,
                             f16* __restrict__ oh, f16* __restrict__ ol,
                             int K, int N) {
    __shared__ float tile[32][33];
    int z = blockIdx.z;
    const float* Wz = W + (size_t)z * K * N;
    size_t ob = (size_t)z * K * N;
    int kb = blockIdx.y * 32, nb = blockIdx.x * 32;
    int tx = threadIdx.x, ty = threadIdx.y;
#pragma unroll
    for (int i = 0; i < 4; i++)
        tile[ty + 8 * i][tx] = Wz[(size_t)(kb + ty + 8 * i) * N + nb + tx];
    __syncthreads();
#pragma unroll
    for (int i = 0; i < 4; i++) {
        float v = tile[tx][ty + 8 * i];
        f16 h = __float2half_rn(v);
        size_t o = ob + (size_t)(nb + ty + 8 * i) * K + kb + tx;
        oh[o] = h;
        if (ol) ol[o] = __float2half_rn(v - __half2float(h));
    }
}

// ---------------------------------------------------------------------------
// Embedding gather
// ---------------------------------------------------------------------------
__global__ void embed_kernel(const int* __restrict__ ids,
                             const float* __restrict__ wte,
                             float* __restrict__ x) {
    int row = blockIdx.x;
    int tok = ids[row];
    const float4* src = (const float4*)(wte + (size_t)tok * Dd);
    float4* dst = (float4*)(x + (size_t)row * Dd);
    for (int i = threadIdx.x; i < Dd / 4; i += blockDim.x) dst[i] = src[i];
}

// ---------------------------------------------------------------------------
// LayerNorm -> fp16
// ---------------------------------------------------------------------------
__global__ void ln_kernel(const float* __restrict__ x,
                          const float* __restrict__ gamma,
                          const float* __restrict__ beta,
                          f16* __restrict__ oh) {
    int row = blockIdx.x;
    const float* xr = x + (size_t)row * Dd;
    int t = threadIdx.x;
    float v[4];
    float s = 0.f, sq = 0.f;
#pragma unroll
    for (int i = 0; i < 4; i++) {
        float val = xr[t + i * 256];
        v[i] = val; s += val; sq += val * val;
    }
#pragma unroll
    for (int o = 16; o > 0; o >>= 1) {
        s  += __shfl_xor_sync(0xFFFFFFFFu, s, o);
        sq += __shfl_xor_sync(0xFFFFFFFFu, sq, o);
    }
    __shared__ float ss[8], sqq[8];
    int wid = t >> 5, lane = t & 31;
    if (lane == 0) { ss[wid] = s; sqq[wid] = sq; }
    __syncthreads();
    if (t == 0) {
        float a = 0.f, b = 0.f;
#pragma unroll
        for (int i = 0; i < 8; i++) { a += ss[i]; b += sqq[i]; }
        ss[0] = a; sqq[0] = b;
    }
    __syncthreads();
    float mean = ss[0] * (1.0f / Dd);
    float var  = sqq[0] * (1.0f / Dd) - mean * mean;
    float inv  = rsqrtf(var + 1e-5f);
#pragma unroll
    for (int i = 0; i < 4; i++) {
        int c = t + i * 256;
        float o = (v[i] - mean) * inv * gamma[c] + beta[c];
        oh[(size_t)row * Dd + c] = __float2half_rn(o);
    }
}

// ---------------------------------------------------------------------------
// RoPE in place on qkv (fp32)
// ---------------------------------------------------------------------------
__global__ void rope_kernel(float* __restrict__ qkv) {
    int row = blockIdx.x;
    int t = row % Tt;
    float* qr = qkv + (size_t)row * QKVD;
    const float ft = (float)t;
    for (int idx = threadIdx.x; idx < (Hh + KVHh) * (HDd / 2); idx += blockDim.x) {
        int head = idx >> 5;
        int i    = idx & 31;
        int base = (head < Hh) ? head * HDd : Dd + (head - Hh) * HDd;
        float inv = expf(-((2.0f * i) / (float)HDd) * 9.210340371976184f);
        float ang = ft * inv;
        float c, s;
        sincosf(ang, &s, &c);
        float u0 = qr[base + 2 * i];
        float u1 = qr[base + 2 * i + 1];
        qr[base + 2 * i]     = u0 * c - u1 * s;
        qr[base + 2 * i + 1] = u0 * s + u1 * c;
    }
}

// ---------------------------------------------------------------------------
// Causal flash attention: 256 threads = 64 q-rows x 4 GQA heads sharing one
// KV head's tiles. Tile-max softmax (one rescale per 64-key tile).
// grid: (T/64, KVH, B).
// ---------------------------------------------------------------------------
#define ATTN_SMEM ((4096 + 4096 + 4 * 64 * 65) * 4)

__global__ void __launch_bounds__(256) attn_kernel(const float* __restrict__ qkv,
                                                   f16* __restrict__ y) {
    extern __shared__ float asm_[];
    float* Ks = asm_;                 // [64][64]
    float* Vs = asm_ + 4096;          // [64][64]
    float* S  = asm_ + 8192;          // [4][64][65]

    int qt = blockIdx.x, kvh = blockIdx.y, b = blockIdx.z;
    int tid = threadIdx.x;
    int qr = tid & 63;                // query row within tile
    int hsub = tid >> 6;              // 0..3
    int h = kvh * 4 + hsub;           // q head (h/4 == kvh)
    int qglob = qt * 64 + qr;
    int qrow = b * Tt + qglob;
    const float* qp = qkv + (size_t)qrow * QKVD + h * HDd;

    float q[HDd];
#pragma unroll
    for (int d = 0; d < HDd; d++) q[d] = qp[d];
    float acc[HDd];
#pragma unroll
    for (int d = 0; d < HDd; d++) acc[d] = 0.f;
    float m = -1e30f, l = 0.f;

    float* Srow = S + (hsub * 64 + qr) * 65;

    const float* Kbase = qkv + (size_t)(b * Tt) * QKVD + Dd + kvh * HDd;
    const float* Vbase = Kbase + KVHh * HDd;
    const float scale = 0.125f;

    for (int kt = 0; kt <= qt; kt++) {
        const float* Kb = Kbase + (size_t)kt * 64 * QKVD;
        const float* Vb = Vbase + (size_t)kt * 64 * QKVD;
        __syncthreads();
        for (int id = tid; id < 2048; id += 256) {
            int r = (id & 1023) >> 4, dg = id & 15;
            float* dst = (id < 1024) ? Ks : Vs;
            const float* src = (id < 1024) ? Kb : Vb;
            ((float4*)(dst + r * 64))[dg] = *(const float4*)(src + (size_t)r * QKVD + dg * 4);
        }
        __syncthreads();
        int jmax = (kt == qt) ? (qr + 1) : 64;
        float tmax = -1e30f;
        for (int j = 0; j < jmax; j++) {
            float s = 0.f;
            const float* kr = Ks + j * 64;
#pragma unroll
            for (int d = 0; d < HDd; d++) s += q[d] * kr[d];
            s *= scale;
            Srow[j] = s;
            tmax = fmaxf(tmax, s);
        }
        if (tmax > m) {
            float corr = __expf(m - tmax);
            l *= corr;
#pragma unroll
            for (int d = 0; d < HDd; d++) acc[d] *= corr;
            m = tmax;
        }
        for (int j = 0; j < jmax; j++) {
            float p = __expf(Srow[j] - m);
            l += p;
            const float* vr = Vs + j * 64;
#pragma unroll
            for (int d = 0; d < HDd; d++) acc[d] += p * vr[d];
        }
    }
    float invl = 1.f / l;
    size_t yo = (size_t)qrow * Dd + h * HDd;
#pragma unroll
    for (int d = 0; d < HDd; d++)
        y[yo + d] = __float2half_rn(acc[d] * invl);
}

// ---------------------------------------------------------------------------
// GEMM (fp16, PASSES-compensated): C[M,N] = A[M,K] @ W[N,K]^T (+bias, epilogue)
//   A fp16 single; W split hi(+lo when PASSES==2). fp32 accumulate.
// Grid: (BT/128, N/256), 256 threads.
//   - tcgen05 path (feature arch): tile 128x256, BK=64, TMEM accum
//   - mma.sync fallback (R6 config): two 128-col halves, BK=32, 2-stage,
//     warp tile 64x32, LDS.32 fragment loads
// EPI 0: bias + fp32 out.  EPI 1: bias + GELU + fp16 out.  EPI 2: bias+res+fp32.
// ---------------------------------------------------------------------------
#if defined(__CUDA_ARCH_FEAT_SM103_ALL) || defined(__CUDA_ARCH_FEAT_SM100_ALL) || defined(__CUDA_ARCH_FEAT_SM101_ALL)
#define HAS_TCGEN05 1
#else
#define HAS_TCGEN05 0
#endif

#define TM 128
#define TN 256
// tcgen05 path smem: A 16KB + Wh 32KB + Wl 32KB per stage, 2 stages, +1KB ctrl
#define TC_STG   81920u
#define TC_OFF_A 0u
#define TC_OFF_BH 16384u
#define TC_OFF_BL 49152u
#define TILE_OFF 1024u
#define GEMM_SMEM_TOTAL (1024 + 2 * 81920)

// idesc kind::f16 (fp16 in, fp32 accum): dtype=F32(1<<4), atype=btype=F16(0)
#define GEMM_IDESC ((1u << 4) | ((TN / 8u) << 17) | ((TM / 16u) << 24))

// SW128 descriptor: layout=2, version=1, SBO=64, LBO=1
#define DESC_BASE ((2ull << 61) | (1ull << 46) | (64ull << 32) | (1ull << 16))
#define MAKE_DESC(addr) (DESC_BASE | (((uint64_t)((addr) >> 4)) & 0x3FFF))

__device__ __forceinline__ void cpasync16(uint32_t d, const void* src) {
    asm volatile("cp.async.cg.shared.global [%0], [%1], 16;\n" :: "r"(d), "l"(src));
}
__device__ __forceinline__ void cpasync16p(void* dst, const void* src) {
    uint32_t d = (uint32_t)__cvta_generic_to_shared(dst);
    asm volatile("cp.async.cg.shared.global [%0], [%1], 16;\n" :: "r"(d), "l"(src));
}

#define MMAF16(d, a, b)                                                       \
    asm volatile(                                                             \
        "mma.sync.aligned.m16n8k16.row.col.f32.f16.f16.f32 "                  \
        "{%0,%1,%2,%3}, {%4,%5,%6,%7}, {%8,%9}, {%0,%1,%2,%3};"               \
        : "+f"((d)[0]), "+f"((d)[1]), "+f"((d)[2]), "+f"((d)[3])              \
        : "r"((a)[0]), "r"((a)[1]), "r"((a)[2]), "r"((a)[3]),                 \
          "r"((b)[0]), "r"((b)[1]))

#if HAS_TCGEN05
__device__ __forceinline__ void tc_mma(uint32_t d, uint64_t a, uint64_t b, uint32_t en) {
    asm volatile(
        "{\n\t.reg .pred p;\n\tsetp.ne.u32 p, %4, 0;\n\t"
        "tcgen05.mma.cta_group::1.kind::f16 [%0], %1, %2, %3, {%5,%5,%5,%5}, p;\n\t}"
        :: "r"(d), "l"(a), "l"(b), "r"(GEMM_IDESC), "r"(en), "r"(0u) : "memory");
}
__device__ __forceinline__ void mbar_wait(uint32_t mbar, uint32_t parity) {
    uint32_t done;
    asm volatile(
        "{\n\t.reg .pred p;\n\t"
        "mbarrier.try_wait.parity.acquire.cta.shared::cta.b64 p, [%1], %2;\n\t"
        "selp.b32 %0, 1, 0, p;\n\t}"
        : "=r"(done) : "r"(mbar), "r"(parity) : "memory");
    if (!done) {
        asm volatile(
            "{\n\t.reg .pred P1;\n\t"
            "WL_%=:\n\t"
            "mbarrier.try_wait.parity.acquire.cta.shared::cta.b64 P1, [%0], %1, 0x989680;\n\t"
            "@P1 bra.uni WD_%=;\n\t"
            "bra.uni WL_%=;\n\t"
            "WD_%=:\n\t}"
            :: "r"(mbar), "r"(parity) : "memory");
    }
}
__device__ __forceinline__ void tc_load_stage(
    uint32_t stg, const f16* A, const f16* Wh, const f16* Wl,
    int rowBase, int colBase, int K, int kt, int tid, int nchunks) {
    for (int id = tid; id < nchunks; id += 256) {
        const f16* src; uint32_t off; int r, c, rg;
        if (id < 1024) {
            r = id >> 3; c = id & 7;
            src = A; off = TC_OFF_A; rg = rowBase + r;
        } else {
            int t2 = id - 1024;
            int q = t2 & 2047; r = q >> 3; c = q & 7;
            bool hi = t2 < 2048;
            src = hi ? Wh : Wl; off = hi ? TC_OFF_BH : TC_OFF_BL;
            rg = colBase + r;
        }
        int bo = r * 128 + c * 16;
        uint32_t sw = (uint32_t)(bo ^ ((bo >> 3) & 0x70));
        cpasync16(stg + off + sw, src + (size_t)rg * K + kt + c * 8);
    }
}
#endif

template <int EPI, int PASSES>
__global__ void __launch_bounds__(256) gemm_any(
    const f16* __restrict__ A, const f16* __restrict__ Wh, const f16* __restrict__ Wl,
    const float* __restrict__ bias, const float* __restrict__ res,
    float* __restrict__ C, f16* __restrict__ Cout, int N, int K) {
    extern __shared__ __align__(1024) char sm[];
    const int tid = threadIdx.x;
    const int wid = tid >> 5, lane = tid & 31;
    const int rowBase = blockIdx.x * TM;
    const int colBase = blockIdx.y * TN;

#if HAS_TCGEN05
    // ---------------- tcgen05 path ----------------
    uint32_t smb;
    asm("{ .reg .u64 t; cvta.to.shared.u64 t, %1; cvt.u32.u64 %0, t; }"
        : "=r"(smb) : "l"(sm));
    if (wid == 0)
        asm volatile("tcgen05.alloc.cta_group::1.sync.aligned.shared::cta.b32 [%0], %1;"
                     :: "r"(smb), "r"(256) : "memory");
    if (tid == 0) {
        asm volatile("mbarrier.init.shared.b64 [%0], 1;" :: "r"(smb + 8)  : "memory");
        asm volatile("mbarrier.init.shared.b64 [%0], 1;" :: "r"(smb + 16) : "memory");
    }
    __syncthreads();
    uint32_t tmem;
    asm volatile("ld.shared.b32 %0, [%1];" : "=r"(tmem) : "r"(smb));

    const int nchunks = (PASSES == 2) ? 5120 : 3072;
    const int niter = K >> 6;
    tc_load_stage(smb + TILE_OFF, A, Wh, Wl, rowBase, colBase, K, 0, tid, nchunks);
    asm volatile("cp.async.commit_group;");
    tc_load_stage(smb + TILE_OFF + TC_STG, A, Wh, Wl, rowBase, colBase, K, 64, tid, nchunks);
    asm volatile("cp.async.commit_group;");

    for (int it = 0; it < niter; ++it) {
        const int s = it & 1;
        const uint32_t stg = smb + TILE_OFF + s * TC_STG;
        asm volatile("cp.async.wait_group 1;");
        __syncthreads();
        if (tid == 0) {
            asm volatile("fence.proxy.async.shared::cta;" ::: "memory");
            uint64_t ad = MAKE_DESC(stg + TC_OFF_A);
            uint64_t bh = MAKE_DESC(stg + TC_OFF_BH);
            uint64_t bl = MAKE_DESC(stg + TC_OFF_BL);
#pragma unroll
            for (int k = 0; k < 4; ++k) {
                tc_mma(tmem, ad + k * 2, bh + k * 2, (it | k) ? 1u : 0u);
                if (PASSES == 2) tc_mma(tmem, ad + k * 2, bl + k * 2, 1u);
            }
            asm volatile(
                "tcgen05.commit.cta_group::1.mbarrier::arrive::one.shared::cluster.b64 [%0];"
                :: "r"(smb + 8 + s * 8) : "memory");
        }
        mbar_wait(smb + 8 + s * 8, (uint32_t)((it >> 1) & 1));
        if (it + 2 < niter)
            tc_load_stage(stg, A, Wh, Wl, rowBase, colBase, K, (it + 2) * 64, tid, nchunks);
        asm volatile("cp.async.commit_group;");
    }
    __syncthreads();
    asm volatile("tcgen05.fence::after_thread_sync;" ::: "memory");

    float* tsm = (float*)(sm + TILE_OFF) + wid * (32 * 33);
    const int sub = wid & 3;
    const int cwbase = (wid >= 4) ? 128 : 0;
#pragma unroll 1
    for (int ch = 0; ch < 4; ++ch) {
        int c0 = cwbase + ch * 32;
        uint32_t d[32];
        asm volatile(
            "tcgen05.ld.sync.aligned.32x32b.x32.b32 "
            "{%0,%1,%2,%3,%4,%5,%6,%7,%8,%9,%10,%11,%12,%13,%14,%15,"
            "%16,%17,%18,%19,%20,%21,%22,%23,%24,%25,%26,%27,%28,%29,%30,%31}, [%32];"
            : "=r"(d[0]), "=r"(d[1]), "=r"(d[2]), "=r"(d[3]), "=r"(d[4]), "=r"(d[5]),
              "=r"(d[6]), "=r"(d[7]), "=r"(d[8]), "=r"(d[9]), "=r"(d[10]), "=r"(d[11]),
              "=r"(d[12]), "=r"(d[13]), "=r"(d[14]), "=r"(d[15]), "=r"(d[16]), "=r"(d[17]),
              "=r"(d[18]), "=r"(d[19]), "=r"(d[20]), "=r"(d[21]), "=r"(d[22]), "=r"(d[23]),
              "=r"(d[24]), "=r"(d[25]), "=r"(d[26]), "=r"(d[27]), "=r"(d[28]), "=r"(d[29]),
              "=r"(d[30]), "=r"(d[31])
            : "r"(tmem + c0));
        asm volatile("tcgen05.wait::ld.sync.aligned;" ::: "memory");
#pragma unroll
        for (int j = 0; j < 32; ++j) {
            float x = __uint_as_float(d[j]);
            if (bias) x += bias[colBase + c0 + j];
            if (EPI == 1) x = 0.5f * x * (1.f + erff(x * 0.70710678118654752f));
            tsm[lane * 33 + j] = x;
        }
        __syncwarp();
#pragma unroll
        for (int jj = 0; jj < 32; ++jj) {
            int r = rowBase + sub * 32 + jj;
            int c = colBase + c0 + lane;
            float val = tsm[jj * 33 + lane];
            if (EPI == 1) {
                Cout[(size_t)r * N + c] = __float2half_rn(val);
            } else {
                if (EPI == 2) val += res[(size_t)r * N + c];
                C[(size_t)r * N + c] = val;
            }
        }
        __syncwarp();
    }
    __syncthreads();
    if (wid == 0)
        asm volatile("tcgen05.dealloc.cta_group::1.sync.aligned.b32 %0, %1;"
                     :: "r"(tmem), "r"(256));

#else
    // -------- mma.sync fallback (R6): two 128-col halves, BK=32, LDS --------
    const int warpM = wid >> 2, warpN = wid & 3;   // 2 x 4 warps, tile 64x32
    f16* smh = (f16*)sm;
    const int LDA = 40;           // 32 + 8 pad (halves)
    const int SCH = 128 * 40;     // halves per array (5120)
    const int SST = 3 * SCH;      // halves per stage (15360)
    const int niter = K >> 5;
    const int NPRE = (PASSES == 2) ? 6 : 4;   // 16B chunks: 1536 or 1024

    for (int hf = 0; hf < 2; ++hf) {
        const int cb = colBase + hf * 128;
        float acc[4][4][4];
#pragma unroll
        for (int a = 0; a < 4; a++)
#pragma unroll
            for (int b = 0; b < 4; b++)
#pragma unroll
                for (int c = 0; c < 4; c++) acc[a][b][c] = 0.f;

#define FB_PREFETCH(stage, kt)                                                \
        {                                                                     \
            f16* sb = smh + (stage) * SST;                                    \
            _Pragma("unroll")                                                 \
            for (int u = 0; u < NPRE; ++u) {                                  \
                int id = tid + u * 256;                                       \
                int arr = id >> 9;                                            \
                int q = id & 511;                                             \
                int r = q >> 2, seg = q & 3;                                  \
                const f16* src = (arr == 0) ? A : ((arr == 1) ? Wh : Wl);     \
                int rg = ((arr == 0) ? rowBase : cb) + r;                     \
                cpasync16p(sb + arr * SCH + r * LDA + seg * 8,                \
                           src + (size_t)rg * K + (kt) + seg * 8);            \
            }                                                                 \
            asm volatile("cp.async.commit_group;");                           \
        }

        FB_PREFETCH(0, 0);

        for (int it = 0; it < niter; ++it) {
            if (it + 1 < niter) {
                FB_PREFETCH((it + 1) & 1, (it + 1) << 5);
                asm volatile("cp.async.wait_group 1;");
            } else {
                asm volatile("cp.async.wait_group 0;");
            }
            __syncthreads();

            const f16* sA  = smh + (it & 1) * SST;
            const f16* sBh = sA + SCH;
            const f16* sBl = sA + 2 * SCH;

#pragma unroll
            for (int k0 = 0; k0 < 32; k0 += 16) {
                uint32_t ah[4][4], bh[4][2], bl[4][2];
                const int col = k0 + (lane & 3) * 2;
#pragma unroll
                for (int mt = 0; mt < 4; ++mt) {
                    int r = warpM * 64 + mt * 16 + (lane >> 2);
                    const f16* p = sA + r * LDA + col;
                    ah[mt][0] = *(const uint32_t*)p;
                    ah[mt][1] = *(const uint32_t*)(p + 8 * LDA);
                    ah[mt][2] = *(const uint32_t*)(p + 8);
                    ah[mt][3] = *(const uint32_t*)(p + 8 * LDA + 8);
                }
#pragma unroll
                for (int nt = 0; nt < 4; ++nt) {
                    int n = warpN * 32 + nt * 8 + (lane >> 2);
                    const f16* p = sBh + n * LDA + col;
                    bh[nt][0] = *(const uint32_t*)p;
                    bh[nt][1] = *(const uint32_t*)(p + 8);
                    if (PASSES == 2) {
                        const f16* q = sBl + n * LDA + col;
                        bl[nt][0] = *(const uint32_t*)q;
                        bl[nt][1] = *(const uint32_t*)(q + 8);
                    }
                }
#pragma unroll
                for (int mt = 0; mt < 4; ++mt)
#pragma unroll
                    for (int nt = 0; nt < 4; ++nt) {
                        MMAF16(acc[mt][nt], ah[mt], bh[nt]);
                        if (PASSES == 2) MMAF16(acc[mt][nt], ah[mt], bl[nt]);
                    }
            }
            __syncthreads();
        }
#undef FB_PREFETCH

        // Epilogue for this half
#pragma unroll
        for (int mt = 0; mt < 4; ++mt) {
#pragma unroll
            for (int nt = 0; nt < 4; ++nt) {
                int r0 = rowBase + warpM * 64 + mt * 16 + (lane >> 2);
                int c0 = cb + warpN * 32 + nt * 8 + (lane & 3) * 2;
                float v0 = acc[mt][nt][0], v1 = acc[mt][nt][1];
                float v2 = acc[mt][nt][2], v3 = acc[mt][nt][3];
                if (bias) {
                    float b0 = bias[c0], b1 = bias[c0 + 1];
                    v0 += b0; v1 += b1; v2 += b0; v3 += b1;
                }
                if (EPI == 1) {
                    v0 = 0.5f * v0 * (1.f + erff(v0 * 0.70710678118654752f));
                    v1 = 0.5f * v1 * (1.f + erff(v1 * 0.70710678118654752f));
                    v2 = 0.5f * v2 * (1.f + erff(v2 * 0.70710678118654752f));
                    v3 = 0.5f * v3 * (1.f + erff(v3 * 0.70710678118654752f));
                    __half2 p0, p1;
                    p0.x = __float2half_rn(v0); p0.y = __float2half_rn(v1);
                    p1.x = __float2half_rn(v2); p1.y = __float2half_rn(v3);
                    *(__half2*)(Cout + (size_t)r0 * N + c0) = p0;
                    *(__half2*)(Cout + (size_t)(r0 + 8) * N + c0) = p1;
                } else {
                    if (EPI == 2) {
                        float2 ra = *(const float2*)(res + (size_t)r0 * N + c0);
                        float2 rb = *(const float2*)(res + (size_t)(r0 + 8) * N + c0);
                        v0 += ra.x; v1 += ra.y; v2 += rb.x; v3 += rb.y;
                    }
                    float2 o0; o0.x = v0; o0.y = v1;
                    float2 o1; o1.x = v2; o1.y = v3;
                    *(float2*)(C + (size_t)r0 * N + c0) = o0;
                    *(float2*)(C + (size_t)(r0 + 8) * N + c0) = o1;
                }
            }
        }
        __syncthreads();
    }
#endif
}

// ---------------------------------------------------------------------------
// Launch
// ---------------------------------------------------------------------------
extern "C" void kernel_launch(void* const* d_in, const int* in_sizes, int n_in,
                              void* d_out, int out_size) {
    const int*   ids      = (const int*)d_in[0];
    const float* wte      = (const float*)d_in[1];
    const float* ln1_g    = (const float*)d_in[2];
    const float* ln1_b    = (const float*)d_in[3];
    const float* c_attn_w = (const float*)d_in[4];
    const float* c_attn_b = (const float*)d_in[5];
    const float* c_proj_w = (const float*)d_in[6];
    const float* c_proj_b = (const float*)d_in[7];
    const float* ln2_g    = (const float*)d_in[8];
    const float* ln2_b    = (const float*)d_in[9];
    const float* fc_w     = (const float*)d_in[10];
    const float* fc_b     = (const float*)d_in[11];
    const float* proj_w   = (const float*)d_in[12];
    const float* proj_b   = (const float*)d_in[13];
    const float* lnf_g    = (const float*)d_in[14];
    const float* lnf_b    = (const float*)d_in[15];
    const float* lm_w     = (const float*)d_in[16];
    float* out = (float*)d_out;

    float *x, *qkv;
    f16 *h, *y, *mlp;
    f16 *wqkv_hi, *wqkv_lo, *wap_hi, *wap_lo, *wfc_hi, *wfc_lo;
    f16 *wmp_hi, *wmp_lo, *wlm_hi;
    cudaGetSymbolAddress((void**)&x,    g_x);
    cudaGetSymbolAddress((void**)&qkv,  g_qkv);
    cudaGetSymbolAddress((void**)&h,    g_h);
    cudaGetSymbolAddress((void**)&y,    g_y);
    cudaGetSymbolAddress((void**)&mlp,  g_mlp);
    cudaGetSymbolAddress((void**)&wqkv_hi, g_wqkv_hi);
    cudaGetSymbolAddress((void**)&wqkv_lo, g_wqkv_lo);
    cudaGetSymbolAddress((void**)&wap_hi,  g_wap_hi);
    cudaGetSymbolAddress((void**)&wap_lo,  g_wap_lo);
    cudaGetSymbolAddress((void**)&wfc_hi,  g_wfc_hi);
    cudaGetSymbolAddress((void**)&wfc_lo,  g_wfc_lo);
    cudaGetSymbolAddress((void**)&wmp_hi,  g_wmp_hi);
    cudaGetSymbolAddress((void**)&wmp_lo,  g_wmp_lo);
    cudaGetSymbolAddress((void**)&wlm_hi,  g_wlm_hi);

    cudaFuncSetAttribute(gemm_any<0, 2>, cudaFuncAttributeMaxDynamicSharedMemorySize, GEMM_SMEM_TOTAL);
    cudaFuncSetAttribute(gemm_any<0, 1>, cudaFuncAttributeMaxDynamicSharedMemorySize, GEMM_SMEM_TOTAL);
    cudaFuncSetAttribute(gemm_any<1, 2>, cudaFuncAttributeMaxDynamicSharedMemorySize, GEMM_SMEM_TOTAL);
    cudaFuncSetAttribute(gemm_any<2, 2>, cudaFuncAttributeMaxDynamicSharedMemorySize, GEMM_SMEM_TOTAL);
    cudaFuncSetAttribute(attn_kernel, cudaFuncAttributeMaxDynamicSharedMemorySize, ATTN_SMEM);

    dim3 t32x8(32, 8);

    // Weight conversion (transpose + split; LM head hi-only)
    wconv_kernel<<<dim3(QKVD / 32, Dd / 32, Ll), t32x8>>>(c_attn_w, wqkv_hi, wqkv_lo, Dd, QKVD);
    wconv_kernel<<<dim3(Dd / 32, Dd / 32, Ll),   t32x8>>>(c_proj_w, wap_hi,  wap_lo,  Dd, Dd);
    wconv_kernel<<<dim3(FFd / 32, Dd / 32, Ll),  t32x8>>>(fc_w,     wfc_hi,  wfc_lo,  Dd, FFd);
    wconv_kernel<<<dim3(Dd / 32, FFd / 32, Ll),  t32x8>>>(proj_w,   wmp_hi,  wmp_lo,  FFd, Dd);
    wconv_kernel<<<dim3(Vv / 32, Dd / 32, 1),    t32x8>>>(lm_w,     wlm_hi,  nullptr, Dd, Vv);

    embed_kernel<<<BT, 256>>>(ids, wte, x);

    for (int l = 0; l < Ll; l++) {
        // LN1 -> h (fp16)
        ln_kernel<<<BT, 256>>>(x, ln1_g + (size_t)l * Dd, ln1_b + (size_t)l * Dd, h);
        // QKV projection (fp32 out)
        gemm_any<0, 2><<<dim3(BT / TM, QKVD / TN), 256, GEMM_SMEM_TOTAL>>>(
            h, wqkv_hi + (size_t)l * QKVD * Dd, wqkv_lo + (size_t)l * QKVD * Dd,
            c_attn_b + (size_t)l * QKVD, nullptr, qkv, nullptr, QKVD, Dd);
        // RoPE
        rope_kernel<<<BT, 256>>>(qkv);
        // Attention -> y (fp16)
        attn_kernel<<<dim3(Tt / 64, KVHh, Bq), 256, ATTN_SMEM>>>(qkv, y);
        // Attn out projection + residual (fp32 into x)
        gemm_any<2, 2><<<dim3(BT / TM, Dd / TN), 256, GEMM_SMEM_TOTAL>>>(
            y, wap_hi + (size_t)l * Dd * Dd, wap_lo + (size_t)l * Dd * Dd,
            c_proj_b + (size_t)l * Dd, x, x, nullptr, Dd, Dd);
        // LN2 -> h (fp16)
        ln_kernel<<<BT, 256>>>(x, ln2_g + (size_t)l * Dd, ln2_b + (size_t)l * Dd, h);
        // FC + GELU -> mlp (fp16)
        gemm_any<1, 2><<<dim3(BT / TM, FFd / TN), 256, GEMM_SMEM_TOTAL>>>(
            h, wfc_hi + (size_t)l * FFd * Dd, wfc_lo + (size_t)l * FFd * Dd,
            fc_b + (size_t)l * FFd, nullptr, nullptr, mlp, FFd, Dd);
        // MLP projection + residual (fp32 into x)
        gemm_any<2, 2><<<dim3(BT / TM, Dd / TN), 256, GEMM_SMEM_TOTAL>>>(
            mlp, wmp_hi + (size_t)l * Dd * FFd, wmp_lo + (size_t)l * Dd * FFd,
            proj_b + (size_t)l * Dd, x, x, nullptr, Dd, FFd);
    }

    // Final LN + LM head (single-pass fp16 weights)
    ln_kernel<<<BT, 256>>>(x, lnf_g, lnf_b, h);
    gemm_any<0, 1><<<dim3(BT / TM, Vv / TN), 256, GEMM_SMEM_TOTAL>>>(
        h, wlm_hi, nullptr, nullptr, nullptr, out, nullptr, Vv, Dd);
}

// round 11
// speedup vs baseline: 1.8028x; 1.0619x over previous
#include <cuda_runtime.h>
#include <cuda_fp16.h>
#include <math.h>
#include <stdint.h>

// Problem constants
#define Bq    8
#define Tt    512
#define BT    4096      // B*T
#define Dd    1024
#define Hh    16
#define KVHh  4
#define HDd   64
#define Ll    4
#define Vv    32000
#define FFd   4096
#define QKVD  1536      // H*HD + 2*KVH*HD

typedef __half f16;

// ---------------------------------------------------------------------------
// Scratch (static device globals; no allocations allowed)
// ---------------------------------------------------------------------------
__device__ float g_x[BT * Dd];        // residual stream (fp32)
__device__ float g_qkv[BT * QKVD];    // qkv projection (rope in place, fp32)

__device__ f16 g_h[BT * Dd];          // layernorm output (fp16)
__device__ f16 g_y[BT * Dd];          // attention output (fp16)
__device__ f16 g_mlp[BT * FFd];       // gelu(fc) output (fp16)

// Transposed + split weights ([N][K] layout, fp16 hi/lo)
__device__ f16 g_wqkv_hi[Ll * QKVD * Dd];
__device__ f16 g_wqkv_lo[Ll * QKVD * Dd];
__device__ f16 g_wap_hi [Ll * Dd * Dd];     // single-pass (no lo)
__device__ f16 g_wfc_hi [Ll * FFd * Dd];
__device__ f16 g_wfc_lo [Ll * FFd * Dd];
__device__ f16 g_wmp_hi [Ll * Dd * FFd];    // single-pass (no lo)
__device__ f16 g_wlm_hi [Vv * Dd];          // single-pass (no lo)

// ---------------------------------------------------------------------------
// Weight transpose + split:  W[K][N] fp32  ->  out[N][K] fp16 hi(/lo)
// ---------------------------------------------------------------------------
__global__ void wconv_kernel(const float* __restrict__ W,
                             f16* __restrict__ oh, f16* __restrict__ ol,
                             int K, int N) {
    __shared__ float tile[32][33];
    int z = blockIdx.z;
    const float* Wz = W + (size_t)z * K * N;
    size_t ob = (size_t)z * K * N;
    int kb = blockIdx.y * 32, nb = blockIdx.x * 32;
    int tx = threadIdx.x, ty = threadIdx.y;
#pragma unroll
    for (int i = 0; i < 4; i++)
        tile[ty + 8 * i][tx] = Wz[(size_t)(kb + ty + 8 * i) * N + nb + tx];
    __syncthreads();
#pragma unroll
    for (int i = 0; i < 4; i++) {
        float v = tile[tx][ty + 8 * i];
        f16 h = __float2half_rn(v);
        size_t o = ob + (size_t)(nb + ty + 8 * i) * K + kb + tx;
        oh[o] = h;
        if (ol) ol[o] = __float2half_rn(v - __half2float(h));
    }
}

// ---------------------------------------------------------------------------
// Embedding gather
// ---------------------------------------------------------------------------
__global__ void embed_kernel(const int* __restrict__ ids,
                             const float* __restrict__ wte,
                             float* __restrict__ x) {
    int row = blockIdx.x;
    int tok = ids[row];
    const float4* src = (const float4*)(wte + (size_t)tok * Dd);
    float4* dst = (float4*)(x + (size_t)row * Dd);
    for (int i = threadIdx.x; i < Dd / 4; i += blockDim.x) dst[i] = src[i];
}

// ---------------------------------------------------------------------------
// LayerNorm -> fp16
// ---------------------------------------------------------------------------
__global__ void ln_kernel(const float* __restrict__ x,
                          const float* __restrict__ gamma,
                          const float* __restrict__ beta,
                          f16* __restrict__ oh) {
    int row = blockIdx.x;
    const float* xr = x + (size_t)row * Dd;
    int t = threadIdx.x;
    float v[4];
    float s = 0.f, sq = 0.f;
#pragma unroll
    for (int i = 0; i < 4; i++) {
        float val = xr[t + i * 256];
        v[i] = val; s += val; sq += val * val;
    }
#pragma unroll
    for (int o = 16; o > 0; o >>= 1) {
        s  += __shfl_xor_sync(0xFFFFFFFFu, s, o);
        sq += __shfl_xor_sync(0xFFFFFFFFu, sq, o);
    }
    __shared__ float ss[8], sqq[8];
    int wid = t >> 5, lane = t & 31;
    if (lane == 0) { ss[wid] = s; sqq[wid] = sq; }
    __syncthreads();
    if (t == 0) {
        float a = 0.f, b = 0.f;
#pragma unroll
        for (int i = 0; i < 8; i++) { a += ss[i]; b += sqq[i]; }
        ss[0] = a; sqq[0] = b;
    }
    __syncthreads();
    float mean = ss[0] * (1.0f / Dd);
    float var  = sqq[0] * (1.0f / Dd) - mean * mean;
    float inv  = rsqrtf(var + 1e-5f);
#pragma unroll
    for (int i = 0; i < 4; i++) {
        int c = t + i * 256;
        float o = (v[i] - mean) * inv * gamma[c] + beta[c];
        oh[(size_t)row * Dd + c] = __float2half_rn(o);
    }
}

// ---------------------------------------------------------------------------
// RoPE in place on qkv (fp32)
// ---------------------------------------------------------------------------
__global__ void rope_kernel(float* __restrict__ qkv) {
    int row = blockIdx.x;
    int t = row % Tt;
    float* qr = qkv + (size_t)row * QKVD;
    const float ft = (float)t;
    for (int idx = threadIdx.x; idx < (Hh + KVHh) * (HDd / 2); idx += blockDim.x) {
        int head = idx >> 5;
        int i    = idx & 31;
        int base = (head < Hh) ? head * HDd : Dd + (head - Hh) * HDd;
        float inv = expf(-((2.0f * i) / (float)HDd) * 9.210340371976184f);
        float ang = ft * inv;
        float c, s;
        sincosf(ang, &s, &c);
        float u0 = qr[base + 2 * i];
        float u1 = qr[base + 2 * i + 1];
        qr[base + 2 * i]     = u0 * c - u1 * s;
        qr[base + 2 * i + 1] = u0 * s + u1 * c;
    }
}

// ---------------------------------------------------------------------------
// Causal flash attention: 256 threads = 64 q-rows x 4 GQA heads sharing one
// KV head's tiles. Tile-max softmax (one rescale per 64-key tile).
// grid: (T/64, KVH, B).
// ---------------------------------------------------------------------------
#define ATTN_SMEM ((4096 + 4096 + 4 * 64 * 65) * 4)

__global__ void __launch_bounds__(256) attn_kernel(const float* __restrict__ qkv,
                                                   f16* __restrict__ y) {
    extern __shared__ float asm_[];
    float* Ks = asm_;                 // [64][64]
    float* Vs = asm_ + 4096;          // [64][64]
    float* S  = asm_ + 8192;          // [4][64][65]

    int qt = blockIdx.x, kvh = blockIdx.y, b = blockIdx.z;
    int tid = threadIdx.x;
    int qr = tid & 63;                // query row within tile
    int hsub = tid >> 6;              // 0..3
    int h = kvh * 4 + hsub;           // q head (h/4 == kvh)
    int qglob = qt * 64 + qr;
    int qrow = b * Tt + qglob;
    const float* qp = qkv + (size_t)qrow * QKVD + h * HDd;

    float q[HDd];
#pragma unroll
    for (int d = 0; d < HDd; d++) q[d] = qp[d];
    float acc[HDd];
#pragma unroll
    for (int d = 0; d < HDd; d++) acc[d] = 0.f;
    float m = -1e30f, l = 0.f;

    float* Srow = S + (hsub * 64 + qr) * 65;

    const float* Kbase = qkv + (size_t)(b * Tt) * QKVD + Dd + kvh * HDd;
    const float* Vbase = Kbase + KVHh * HDd;
    const float scale = 0.125f;

    for (int kt = 0; kt <= qt; kt++) {
        const float* Kb = Kbase + (size_t)kt * 64 * QKVD;
        const float* Vb = Vbase + (size_t)kt * 64 * QKVD;
        __syncthreads();
        for (int id = tid; id < 2048; id += 256) {
            int r = (id & 1023) >> 4, dg = id & 15;
            float* dst = (id < 1024) ? Ks : Vs;
            const float* src = (id < 1024) ? Kb : Vb;
            ((float4*)(dst + r * 64))[dg] = *(const float4*)(src + (size_t)r * QKVD + dg * 4);
        }
        __syncthreads();
        int jmax = (kt == qt) ? (qr + 1) : 64;
        float tmax = -1e30f;
        for (int j = 0; j < jmax; j++) {
            float s = 0.f;
            const float* kr = Ks + j * 64;
#pragma unroll
            for (int d = 0; d < HDd; d++) s += q[d] * kr[d];
            s *= scale;
            Srow[j] = s;
            tmax = fmaxf(tmax, s);
        }
        if (tmax > m) {
            float corr = __expf(m - tmax);
            l *= corr;
#pragma unroll
            for (int d = 0; d < HDd; d++) acc[d] *= corr;
            m = tmax;
        }
        for (int j = 0; j < jmax; j++) {
            float p = __expf(Srow[j] - m);
            l += p;
            const float* vr = Vs + j * 64;
#pragma unroll
            for (int d = 0; d < HDd; d++) acc[d] += p * vr[d];
        }
    }
    float invl = 1.f / l;
    size_t yo = (size_t)qrow * Dd + h * HDd;
#pragma unroll
    for (int d = 0; d < HDd; d++)
        y[yo + d] = __float2half_rn(acc[d] * invl);
}

// ---------------------------------------------------------------------------
// GEMM (fp16, PASSES-compensated): C[M,N] = A[M,K] @ W[N,K]^T (+bias, epilogue)
//   A fp16 single; W split hi(+lo when PASSES==2). fp32 accumulate.
// Grid: (BT/128, N/256), 256 threads.
//   - tcgen05 path (feature arch): tile 128x256, BK=64, TMEM accum
//   - mma.sync fallback (R6 config): two 128-col halves, BK=32, 2-stage,
//     warp tile 64x32, LDS.32 fragment loads
// EPI 0: bias + fp32 out.  EPI 1: bias + GELU + fp16 out.  EPI 2: bias+res+fp32.
// ---------------------------------------------------------------------------
#if defined(__CUDA_ARCH_FEAT_SM103_ALL) || defined(__CUDA_ARCH_FEAT_SM100_ALL) || defined(__CUDA_ARCH_FEAT_SM101_ALL)
#define HAS_TCGEN05 1
#else
#define HAS_TCGEN05 0
#endif

#define TM 128
#define TN 256
// tcgen05 path smem: A 16KB + Wh 32KB + Wl 32KB per stage, 2 stages, +1KB ctrl
#define TC_STG   81920u
#define TC_OFF_A 0u
#define TC_OFF_BH 16384u
#define TC_OFF_BL 49152u
#define TILE_OFF 1024u
#define GEMM_SMEM_TOTAL (1024 + 2 * 81920)

// idesc kind::f16 (fp16 in, fp32 accum): dtype=F32(1<<4), atype=btype=F16(0)
#define GEMM_IDESC ((1u << 4) | ((TN / 8u) << 17) | ((TM / 16u) << 24))

// SW128 descriptor: layout=2, version=1, SBO=64, LBO=1
#define DESC_BASE ((2ull << 61) | (1ull << 46) | (64ull << 32) | (1ull << 16))
#define MAKE_DESC(addr) (DESC_BASE | (((uint64_t)((addr) >> 4)) & 0x3FFF))

__device__ __forceinline__ void cpasync16(uint32_t d, const void* src) {
    asm volatile("cp.async.cg.shared.global [%0], [%1], 16;\n" :: "r"(d), "l"(src));
}
__device__ __forceinline__ void cpasync16p(void* dst, const void* src) {
    uint32_t d = (uint32_t)__cvta_generic_to_shared(dst);
    asm volatile("cp.async.cg.shared.global [%0], [%1], 16;\n" :: "r"(d), "l"(src));
}

#define MMAF16(d, a, b)                                                       \
    asm volatile(                                                             \
        "mma.sync.aligned.m16n8k16.row.col.f32.f16.f16.f32 "                  \
        "{%0,%1,%2,%3}, {%4,%5,%6,%7}, {%8,%9}, {%0,%1,%2,%3};"               \
        : "+f"((d)[0]), "+f"((d)[1]), "+f"((d)[2]), "+f"((d)[3])              \
        : "r"((a)[0]), "r"((a)[1]), "r"((a)[2]), "r"((a)[3]),                 \
          "r"((b)[0]), "r"((b)[1]))

#if HAS_TCGEN05
__device__ __forceinline__ void tc_mma(uint32_t d, uint64_t a, uint64_t b, uint32_t en) {
    asm volatile(
        "{\n\t.reg .pred p;\n\tsetp.ne.u32 p, %4, 0;\n\t"
        "tcgen05.mma.cta_group::1.kind::f16 [%0], %1, %2, %3, {%5,%5,%5,%5}, p;\n\t}"
        :: "r"(d), "l"(a), "l"(b), "r"(GEMM_IDESC), "r"(en), "r"(0u) : "memory");
}
__device__ __forceinline__ void mbar_wait(uint32_t mbar, uint32_t parity) {
    uint32_t done;
    asm volatile(
        "{\n\t.reg .pred p;\n\t"
        "mbarrier.try_wait.parity.acquire.cta.shared::cta.b64 p, [%1], %2;\n\t"
        "selp.b32 %0, 1, 0, p;\n\t}"
        : "=r"(done) : "r"(mbar), "r"(parity) : "memory");
    if (!done) {
        asm volatile(
            "{\n\t.reg .pred P1;\n\t"
            "WL_%=:\n\t"
            "mbarrier.try_wait.parity.acquire.cta.shared::cta.b64 P1, [%0], %1, 0x989680;\n\t"
            "@P1 bra.uni WD_%=;\n\t"
            "bra.uni WL_%=;\n\t"
            "WD_%=:\n\t}"
            :: "r"(mbar), "r"(parity) : "memory");
    }
}
__device__ __forceinline__ void tc_load_stage(
    uint32_t stg, const f16* A, const f16* Wh, const f16* Wl,
    int rowBase, int colBase, int K, int kt, int tid, int nchunks) {
    for (int id = tid; id < nchunks; id += 256) {
        const f16* src; uint32_t off; int r, c, rg;
        if (id < 1024) {
            r = id >> 3; c = id & 7;
            src = A; off = TC_OFF_A; rg = rowBase + r;
        } else {
            int t2 = id - 1024;
            int q = t2 & 2047; r = q >> 3; c = q & 7;
            bool hi = t2 < 2048;
            src = hi ? Wh : Wl; off = hi ? TC_OFF_BH : TC_OFF_BL;
            rg = colBase + r;
        }
        int bo = r * 128 + c * 16;
        uint32_t sw = (uint32_t)(bo ^ ((bo >> 3) & 0x70));
        cpasync16(stg + off + sw, src + (size_t)rg * K + kt + c * 8);
    }
}
#endif

template <int EPI, int PASSES>
__global__ void __launch_bounds__(256) gemm_any(
    const f16* __restrict__ A, const f16* __restrict__ Wh, const f16* __restrict__ Wl,
    const float* __restrict__ bias, const float* __restrict__ res,
    float* __restrict__ C, f16* __restrict__ Cout, int N, int K) {
    extern __shared__ __align__(1024) char sm[];
    const int tid = threadIdx.x;
    const int wid = tid >> 5, lane = tid & 31;
    const int rowBase = blockIdx.x * TM;
    const int colBase = blockIdx.y * TN;

#if HAS_TCGEN05
    // ---------------- tcgen05 path ----------------
    uint32_t smb;
    asm("{ .reg .u64 t; cvta.to.shared.u64 t, %1; cvt.u32.u64 %0, t; }"
        : "=r"(smb) : "l"(sm));
    if (wid == 0)
        asm volatile("tcgen05.alloc.cta_group::1.sync.aligned.shared::cta.b32 [%0], %1;"
                     :: "r"(smb), "r"(256) : "memory");
    if (tid == 0) {
        asm volatile("mbarrier.init.shared.b64 [%0], 1;" :: "r"(smb + 8)  : "memory");
        asm volatile("mbarrier.init.shared.b64 [%0], 1;" :: "r"(smb + 16) : "memory");
    }
    __syncthreads();
    uint32_t tmem;
    asm volatile("ld.shared.b32 %0, [%1];" : "=r"(tmem) : "r"(smb));

    const int nchunks = (PASSES == 2) ? 5120 : 3072;
    const int niter = K >> 6;
    tc_load_stage(smb + TILE_OFF, A, Wh, Wl, rowBase, colBase, K, 0, tid, nchunks);
    asm volatile("cp.async.commit_group;");
    tc_load_stage(smb + TILE_OFF + TC_STG, A, Wh, Wl, rowBase, colBase, K, 64, tid, nchunks);
    asm volatile("cp.async.commit_group;");

    for (int it = 0; it < niter; ++it) {
        const int s = it & 1;
        const uint32_t stg = smb + TILE_OFF + s * TC_STG;
        asm volatile("cp.async.wait_group 1;");
        __syncthreads();
        if (tid == 0) {
            asm volatile("fence.proxy.async.shared::cta;" ::: "memory");
            uint64_t ad = MAKE_DESC(stg + TC_OFF_A);
            uint64_t bh = MAKE_DESC(stg + TC_OFF_BH);
            uint64_t bl = MAKE_DESC(stg + TC_OFF_BL);
#pragma unroll
            for (int k = 0; k < 4; ++k) {
                tc_mma(tmem, ad + k * 2, bh + k * 2, (it | k) ? 1u : 0u);
                if (PASSES == 2) tc_mma(tmem, ad + k * 2, bl + k * 2, 1u);
            }
            asm volatile(
                "tcgen05.commit.cta_group::1.mbarrier::arrive::one.shared::cluster.b64 [%0];"
                :: "r"(smb + 8 + s * 8) : "memory");
        }
        mbar_wait(smb + 8 + s * 8, (uint32_t)((it >> 1) & 1));
        if (it + 2 < niter)
            tc_load_stage(stg, A, Wh, Wl, rowBase, colBase, K, (it + 2) * 64, tid, nchunks);
        asm volatile("cp.async.commit_group;");
    }
    __syncthreads();
    asm volatile("tcgen05.fence::after_thread_sync;" ::: "memory");

    float* tsm = (float*)(sm + TILE_OFF) + wid * (32 * 33);
    const int sub = wid & 3;
    const int cwbase = (wid >= 4) ? 128 : 0;
#pragma unroll 1
    for (int ch = 0; ch < 4; ++ch) {
        int c0 = cwbase + ch * 32;
        uint32_t d[32];
        asm volatile(
            "tcgen05.ld.sync.aligned.32x32b.x32.b32 "
            "{%0,%1,%2,%3,%4,%5,%6,%7,%8,%9,%10,%11,%12,%13,%14,%15,"
            "%16,%17,%18,%19,%20,%21,%22,%23,%24,%25,%26,%27,%28,%29,%30,%31}, [%32];"
            : "=r"(d[0]), "=r"(d[1]), "=r"(d[2]), "=r"(d[3]), "=r"(d[4]), "=r"(d[5]),
              "=r"(d[6]), "=r"(d[7]), "=r"(d[8]), "=r"(d[9]), "=r"(d[10]), "=r"(d[11]),
              "=r"(d[12]), "=r"(d[13]), "=r"(d[14]), "=r"(d[15]), "=r"(d[16]), "=r"(d[17]),
              "=r"(d[18]), "=r"(d[19]), "=r"(d[20]), "=r"(d[21]), "=r"(d[22]), "=r"(d[23]),
              "=r"(d[24]), "=r"(d[25]), "=r"(d[26]), "=r"(d[27]), "=r"(d[28]), "=r"(d[29]),
              "=r"(d[30]), "=r"(d[31])
            : "r"(tmem + c0));
        asm volatile("tcgen05.wait::ld.sync.aligned;" ::: "memory");
#pragma unroll
        for (int j = 0; j < 32; ++j) {
            float x = __uint_as_float(d[j]);
            if (bias) x += bias[colBase + c0 + j];
            if (EPI == 1) x = 0.5f * x * (1.f + erff(x * 0.70710678118654752f));
            tsm[lane * 33 + j] = x;
        }
        __syncwarp();
#pragma unroll
        for (int jj = 0; jj < 32; ++jj) {
            int r = rowBase + sub * 32 + jj;
            int c = colBase + c0 + lane;
            float val = tsm[jj * 33 + lane];
            if (EPI == 1) {
                Cout[(size_t)r * N + c] = __float2half_rn(val);
            } else {
                if (EPI == 2) val += res[(size_t)r * N + c];
                C[(size_t)r * N + c] = val;
            }
        }
        __syncwarp();
    }
    __syncthreads();
    if (wid == 0)
        asm volatile("tcgen05.dealloc.cta_group::1.sync.aligned.b32 %0, %1;"
                     :: "r"(tmem), "r"(256));

#else
    // -------- mma.sync fallback (R6): two 128-col halves, BK=32, LDS --------
    const int warpM = wid >> 2, warpN = wid & 3;   // 2 x 4 warps, tile 64x32
    f16* smh = (f16*)sm;
    const int LDA = 40;           // 32 + 8 pad (halves)
    const int SCH = 128 * 40;     // halves per array (5120)
    const int SST = 3 * SCH;      // halves per stage (15360)
    const int niter = K >> 5;
    const int NPRE = (PASSES == 2) ? 6 : 4;   // 16B chunks: 1536 or 1024

    for (int hf = 0; hf < 2; ++hf) {
        const int cb = colBase + hf * 128;
        float acc[4][4][4];
#pragma unroll
        for (int a = 0; a < 4; a++)
#pragma unroll
            for (int b = 0; b < 4; b++)
#pragma unroll
                for (int c = 0; c < 4; c++) acc[a][b][c] = 0.f;

#define FB_PREFETCH(stage, kt)                                                \
        {                                                                     \
            f16* sb = smh + (stage) * SST;                                    \
            _Pragma("unroll")                                                 \
            for (int u = 0; u < NPRE; ++u) {                                  \
                int id = tid + u * 256;                                       \
                int arr = id >> 9;                                            \
                int q = id & 511;                                             \
                int r = q >> 2, seg = q & 3;                                  \
                const f16* src = (arr == 0) ? A : ((arr == 1) ? Wh : Wl);     \
                int rg = ((arr == 0) ? rowBase : cb) + r;                     \
                cpasync16p(sb + arr * SCH + r * LDA + seg * 8,                \
                           src + (size_t)rg * K + (kt) + seg * 8);            \
            }                                                                 \
            asm volatile("cp.async.commit_group;");                           \
        }

        FB_PREFETCH(0, 0);

        for (int it = 0; it < niter; ++it) {
            if (it + 1 < niter) {
                FB_PREFETCH((it + 1) & 1, (it + 1) << 5);
                asm volatile("cp.async.wait_group 1;");
            } else {
                asm volatile("cp.async.wait_group 0;");
            }
            __syncthreads();

            const f16* sA  = smh + (it & 1) * SST;
            const f16* sBh = sA + SCH;
            const f16* sBl = sA + 2 * SCH;

#pragma unroll
            for (int k0 = 0; k0 < 32; k0 += 16) {
                uint32_t ah[4][4], bh[4][2], bl[4][2];
                const int col = k0 + (lane & 3) * 2;
#pragma unroll
                for (int mt = 0; mt < 4; ++mt) {
                    int r = warpM * 64 + mt * 16 + (lane >> 2);
                    const f16* p = sA + r * LDA + col;
                    ah[mt][0] = *(const uint32_t*)p;
                    ah[mt][1] = *(const uint32_t*)(p + 8 * LDA);
                    ah[mt][2] = *(const uint32_t*)(p + 8);
                    ah[mt][3] = *(const uint32_t*)(p + 8 * LDA + 8);
                }
#pragma unroll
                for (int nt = 0; nt < 4; ++nt) {
                    int n = warpN * 32 + nt * 8 + (lane >> 2);
                    const f16* p = sBh + n * LDA + col;
                    bh[nt][0] = *(const uint32_t*)p;
                    bh[nt][1] = *(const uint32_t*)(p + 8);
                    if (PASSES == 2) {
                        const f16* q = sBl + n * LDA + col;
                        bl[nt][0] = *(const uint32_t*)q;
                        bl[nt][1] = *(const uint32_t*)(q + 8);
                    }
                }
#pragma unroll
                for (int mt = 0; mt < 4; ++mt)
#pragma unroll
                    for (int nt = 0; nt < 4; ++nt) {
                        MMAF16(acc[mt][nt], ah[mt], bh[nt]);
                        if (PASSES == 2) MMAF16(acc[mt][nt], ah[mt], bl[nt]);
                    }
            }
            __syncthreads();
        }
#undef FB_PREFETCH

        // Epilogue for this half
#pragma unroll
        for (int mt = 0; mt < 4; ++mt) {
#pragma unroll
            for (int nt = 0; nt < 4; ++nt) {
                int r0 = rowBase + warpM * 64 + mt * 16 + (lane >> 2);
                int c0 = cb + warpN * 32 + nt * 8 + (lane & 3) * 2;
                float v0 = acc[mt][nt][0], v1 = acc[mt][nt][1];
                float v2 = acc[mt][nt][2], v3 = acc[mt][nt][3];
                if (bias) {
                    float b0 = bias[c0], b1 = bias[c0 + 1];
                    v0 += b0; v1 += b1; v2 += b0; v3 += b1;
                }
                if (EPI == 1) {
                    v0 = 0.5f * v0 * (1.f + erff(v0 * 0.70710678118654752f));
                    v1 = 0.5f * v1 * (1.f + erff(v1 * 0.70710678118654752f));
                    v2 = 0.5f * v2 * (1.f + erff(v2 * 0.70710678118654752f));
                    v3 = 0.5f * v3 * (1.f + erff(v3 * 0.70710678118654752f));
                    __half2 p0, p1;
                    p0.x = __float2half_rn(v0); p0.y = __float2half_rn(v1);
                    p1.x = __float2half_rn(v2); p1.y = __float2half_rn(v3);
                    *(__half2*)(Cout + (size_t)r0 * N + c0) = p0;
                    *(__half2*)(Cout + (size_t)(r0 + 8) * N + c0) = p1;
                } else {
                    if (EPI == 2) {
                        float2 ra = *(const float2*)(res + (size_t)r0 * N + c0);
                        float2 rb = *(const float2*)(res + (size_t)(r0 + 8) * N + c0);
                        v0 += ra.x; v1 += ra.y; v2 += rb.x; v3 += rb.y;
                    }
                    float2 o0; o0.x = v0; o0.y = v1;
                    float2 o1; o1.x = v2; o1.y = v3;
                    *(float2*)(C + (size_t)r0 * N + c0) = o0;
                    *(float2*)(C + (size_t)(r0 + 8) * N + c0) = o1;
                }
            }
        }
        __syncthreads();
    }
#endif
}

// ---------------------------------------------------------------------------
// Launch
// ---------------------------------------------------------------------------
extern "C" void kernel_launch(void* const* d_in, const int* in_sizes, int n_in,
                              void* d_out, int out_size) {
    const int*   ids      = (const int*)d_in[0];
    const float* wte      = (const float*)d_in[1];
    const float* ln1_g    = (const float*)d_in[2];
    const float* ln1_b    = (const float*)d_in[3];
    const float* c_attn_w = (const float*)d_in[4];
    const float* c_attn_b = (const float*)d_in[5];
    const float* c_proj_w = (const float*)d_in[6];
    const float* c_proj_b = (const float*)d_in[7];
    const float* ln2_g    = (const float*)d_in[8];
    const float* ln2_b    = (const float*)d_in[9];
    const float* fc_w     = (const float*)d_in[10];
    const float* fc_b     = (const float*)d_in[11];
    const float* proj_w   = (const float*)d_in[12];
    const float* proj_b   = (const float*)d_in[13];
    const float* lnf_g    = (const float*)d_in[14];
    const float* lnf_b    = (const float*)d_in[15];
    const float* lm_w     = (const float*)d_in[16];
    float* out = (float*)d_out;

    float *x, *qkv;
    f16 *h, *y, *mlp;
    f16 *wqkv_hi, *wqkv_lo, *wap_hi, *wfc_hi, *wfc_lo, *wmp_hi, *wlm_hi;
    cudaGetSymbolAddress((void**)&x,    g_x);
    cudaGetSymbolAddress((void**)&qkv,  g_qkv);
    cudaGetSymbolAddress((void**)&h,    g_h);
    cudaGetSymbolAddress((void**)&y,    g_y);
    cudaGetSymbolAddress((void**)&mlp,  g_mlp);
    cudaGetSymbolAddress((void**)&wqkv_hi, g_wqkv_hi);
    cudaGetSymbolAddress((void**)&wqkv_lo, g_wqkv_lo);
    cudaGetSymbolAddress((void**)&wap_hi,  g_wap_hi);
    cudaGetSymbolAddress((void**)&wfc_hi,  g_wfc_hi);
    cudaGetSymbolAddress((void**)&wfc_lo,  g_wfc_lo);
    cudaGetSymbolAddress((void**)&wmp_hi,  g_wmp_hi);
    cudaGetSymbolAddress((void**)&wlm_hi,  g_wlm_hi);

    cudaFuncSetAttribute(gemm_any<0, 2>, cudaFuncAttributeMaxDynamicSharedMemorySize, GEMM_SMEM_TOTAL);
    cudaFuncSetAttribute(gemm_any<0, 1>, cudaFuncAttributeMaxDynamicSharedMemorySize, GEMM_SMEM_TOTAL);
    cudaFuncSetAttribute(gemm_any<1, 2>, cudaFuncAttributeMaxDynamicSharedMemorySize, GEMM_SMEM_TOTAL);
    cudaFuncSetAttribute(gemm_any<2, 1>, cudaFuncAttributeMaxDynamicSharedMemorySize, GEMM_SMEM_TOTAL);
    cudaFuncSetAttribute(attn_kernel, cudaFuncAttributeMaxDynamicSharedMemorySize, ATTN_SMEM);

    dim3 t32x8(32, 8);

    // Weight conversion (transpose + split; proj & LM head hi-only)
    wconv_kernel<<<dim3(QKVD / 32, Dd / 32, Ll), t32x8>>>(c_attn_w, wqkv_hi, wqkv_lo, Dd, QKVD);
    wconv_kernel<<<dim3(Dd / 32, Dd / 32, Ll),   t32x8>>>(c_proj_w, wap_hi,  nullptr, Dd, Dd);
    wconv_kernel<<<dim3(FFd / 32, Dd / 32, Ll),  t32x8>>>(fc_w,     wfc_hi,  wfc_lo,  Dd, FFd);
    wconv_kernel<<<dim3(Dd / 32, FFd / 32, Ll),  t32x8>>>(proj_w,   wmp_hi,  nullptr, FFd, Dd);
    wconv_kernel<<<dim3(Vv / 32, Dd / 32, 1),    t32x8>>>(lm_w,     wlm_hi,  nullptr, Dd, Vv);

    embed_kernel<<<BT, 256>>>(ids, wte, x);

    for (int l = 0; l < Ll; l++) {
        // LN1 -> h (fp16)
        ln_kernel<<<BT, 256>>>(x, ln1_g + (size_t)l * Dd, ln1_b + (size_t)l * Dd, h);
        // QKV projection (2-pass, fp32 out)
        gemm_any<0, 2><<<dim3(BT / TM, QKVD / TN), 256, GEMM_SMEM_TOTAL>>>(
            h, wqkv_hi + (size_t)l * QKVD * Dd, wqkv_lo + (size_t)l * QKVD * Dd,
            c_attn_b + (size_t)l * QKVD, nullptr, qkv, nullptr, QKVD, Dd);
        // RoPE
        rope_kernel<<<BT, 256>>>(qkv);
        // Attention -> y (fp16)
        attn_kernel<<<dim3(Tt / 64, KVHh, Bq), 256, ATTN_SMEM>>>(qkv, y);
        // Attn out projection + residual (single-pass, fp32 into x)
        gemm_any<2, 1><<<dim3(BT / TM, Dd / TN), 256, GEMM_SMEM_TOTAL>>>(
            y, wap_hi + (size_t)l * Dd * Dd, nullptr,
            c_proj_b + (size_t)l * Dd, x, x, nullptr, Dd, Dd);
        // LN2 -> h (fp16)
        ln_kernel<<<BT, 256>>>(x, ln2_g + (size_t)l * Dd, ln2_b + (size_t)l * Dd, h);
        // FC + GELU -> mlp (2-pass, fp16 out)
        gemm_any<1, 2><<<dim3(BT / TM, FFd / TN), 256, GEMM_SMEM_TOTAL>>>(
            h, wfc_hi + (size_t)l * FFd * Dd, wfc_lo + (size_t)l * FFd * Dd,
            fc_b + (size_t)l * FFd, nullptr, nullptr, mlp, FFd, Dd);
        // MLP projection + residual (single-pass, fp32 into x)
        gemm_any<2, 1><<<dim3(BT / TM, Dd / TN), 256, GEMM_SMEM_TOTAL>>>(
            mlp, wmp_hi + (size_t)l * Dd * FFd, nullptr,
            proj_b + (size_t)l * Dd, x, x, nullptr, Dd, FFd);
    }

    // Final LN + LM head (single-pass fp16 weights)
    ln_kernel<<<BT, 256>>>(x, lnf_g, lnf_b, h);
    gemm_any<0, 1><<<dim3(BT / TM, Vv / TN), 256, GEMM_SMEM_TOTAL>>>(
        h, wlm_hi, nullptr, nullptr, nullptr, out, nullptr, Vv, Dd);
}